// round 1
// baseline (speedup 1.0000x reference)
#include <cuda_runtime.h>
#include <math.h>

#define N_TOK  16384
#define IN_DIM 1024
#define HID    2048
#define NEXP   8

// Scratch (device globals: allocation-free per harness rules)
__device__ float g_h[(size_t)N_TOK * HID];   // encoded activations
__device__ float g_u[(size_t)N_TOK * HID];   // blended pre-decoder
__device__ int   g_perm[NEXP * N_TOK];       // token ids bucketed by expert
__device__ int   g_counts[NEXP];
__device__ float g_s0[N_TOK];                // coef0 * gate_prob
__device__ float g_s1[N_TOK];                // coef1

__global__ void zero_counts_kernel() {
    if (threadIdx.x < NEXP) g_counts[threadIdx.x] = 0;
}

// ---------------------------------------------------------------------------
// Generic 128x128x8 SIMT fp32 GEMM, 256 threads, 8x8 per thread.
// MODE 0: C = relu(A@B + bias)
// MODE 1: C = (A@B + bias) * rowscale[row]
// MODE 2: C = A@B + bias
// ---------------------------------------------------------------------------
template <int MODE>
__global__ __launch_bounds__(256)
void sgemm128(const float* __restrict__ A, const float* __restrict__ B,
              const float* __restrict__ bias, float* __restrict__ C,
              int M, int N, int K, const float* __restrict__ rowscale)
{
    const int BM = 128, BN = 128, BK = 8, TM = 8, TN = 8;
    __shared__ float As[BK][BM];
    __shared__ float Bs[BK][BN];

    const int tid = threadIdx.x;
    const int bx = blockIdx.x;   // N tile
    const int by = blockIdx.y;   // M tile

    const int threadCol = tid % (BN / TN);  // 0..15
    const int threadRow = tid / (BN / TN);  // 0..15

    const float* Ab = A + (size_t)by * BM * K;
    const float* Bb = B + (size_t)bx * BN;
    float*       Cb = C + (size_t)by * BM * N + (size_t)bx * BN;

    const int innerRowA = tid >> 1;          // 0..127
    const int innerColA = (tid & 1) * 4;     // 0 or 4
    const int innerRowB = tid >> 5;          // 0..7
    const int innerColB = (tid & 31) * 4;    // 0..124

    float acc[TM][TN] = {};
    float regM[TM], regN[TN];

    for (int kt = 0; kt < K; kt += BK) {
        float4 a4 = *(const float4*)(Ab + (size_t)innerRowA * K + kt + innerColA);
        As[innerColA + 0][innerRowA] = a4.x;
        As[innerColA + 1][innerRowA] = a4.y;
        As[innerColA + 2][innerRowA] = a4.z;
        As[innerColA + 3][innerRowA] = a4.w;
        *(float4*)(&Bs[innerRowB][innerColB]) =
            *(const float4*)(Bb + (size_t)(kt + innerRowB) * N + innerColB);
        __syncthreads();

        #pragma unroll
        for (int k = 0; k < BK; k++) {
            #pragma unroll
            for (int i = 0; i < TM; i++) regM[i] = As[k][threadRow * TM + i];
            #pragma unroll
            for (int j = 0; j < TN; j++) regN[j] = Bs[k][threadCol * TN + j];
            #pragma unroll
            for (int i = 0; i < TM; i++)
                #pragma unroll
                for (int j = 0; j < TN; j++)
                    acc[i][j] += regM[i] * regN[j];
        }
        __syncthreads();
    }

    #pragma unroll
    for (int i = 0; i < TM; i++) {
        const int row = threadRow * TM + i;
        float rs = 1.0f;
        if (MODE == 1) rs = rowscale[by * BM + row];
        #pragma unroll
        for (int j = 0; j < TN; j += 4) {
            const int col = threadCol * TN + j;
            float4 b4 = *(const float4*)(bias + (size_t)bx * BN + col);
            float4 v;
            v.x = acc[i][j + 0] + b4.x;
            v.y = acc[i][j + 1] + b4.y;
            v.z = acc[i][j + 2] + b4.z;
            v.w = acc[i][j + 3] + b4.w;
            if (MODE == 0) {
                v.x = fmaxf(v.x, 0.0f); v.y = fmaxf(v.y, 0.0f);
                v.z = fmaxf(v.z, 0.0f); v.w = fmaxf(v.w, 0.0f);
            }
            if (MODE == 1) { v.x *= rs; v.y *= rs; v.z *= rs; v.w *= rs; }
            *(float4*)(Cb + (size_t)row * N + col) = v;
        }
    }
}

// ---------------------------------------------------------------------------
// Grouped expert GEMM: rows gathered via g_perm bucket for expert blockIdx.z.
// C[tok] += (A[tok] @ W_e + b_e) * g_s0[tok]
// ---------------------------------------------------------------------------
__global__ __launch_bounds__(256)
void sgemm128_grouped(const float* __restrict__ A,      // g_h [N_TOK, HID]
                      const float* __restrict__ Wexp,   // [E, HID, HID]
                      const float* __restrict__ bexp,   // [E, HID]
                      float* __restrict__ C)            // g_u accumulate
{
    const int BM = 128, BN = 128, BK = 8, TM = 8, TN = 8;
    const int e   = blockIdx.z;
    const int cnt = g_counts[e];
    const int by  = blockIdx.y;
    const int rowBase = by * BM;
    if (rowBase >= cnt) return;

    __shared__ int   rowmap[BM];
    __shared__ float As[BK][BM];
    __shared__ float Bs[BK][BN];

    const int tid = threadIdx.x;
    const int bx  = blockIdx.x;

    if (tid < BM) {
        int i = rowBase + tid;
        if (i > cnt - 1) i = cnt - 1;      // clamp (stores guarded below)
        rowmap[tid] = g_perm[e * N_TOK + i];
    }
    __syncthreads();

    const int threadCol = tid % (BN / TN);
    const int threadRow = tid / (BN / TN);

    const float* Bb = Wexp + (size_t)e * HID * HID + (size_t)bx * BN;
    const float* bb = bexp + (size_t)e * HID + (size_t)bx * BN;

    const int innerRowA = tid >> 1;
    const int innerColA = (tid & 1) * 4;
    const int innerRowB = tid >> 5;
    const int innerColB = (tid & 31) * 4;

    const int aRow = rowmap[innerRowA];

    float acc[TM][TN] = {};
    float regM[TM], regN[TN];

    for (int kt = 0; kt < HID; kt += BK) {
        float4 a4 = *(const float4*)(A + (size_t)aRow * HID + kt + innerColA);
        As[innerColA + 0][innerRowA] = a4.x;
        As[innerColA + 1][innerRowA] = a4.y;
        As[innerColA + 2][innerRowA] = a4.z;
        As[innerColA + 3][innerRowA] = a4.w;
        *(float4*)(&Bs[innerRowB][innerColB]) =
            *(const float4*)(Bb + (size_t)(kt + innerRowB) * HID + innerColB);
        __syncthreads();

        #pragma unroll
        for (int k = 0; k < BK; k++) {
            #pragma unroll
            for (int i = 0; i < TM; i++) regM[i] = As[k][threadRow * TM + i];
            #pragma unroll
            for (int j = 0; j < TN; j++) regN[j] = Bs[k][threadCol * TN + j];
            #pragma unroll
            for (int i = 0; i < TM; i++)
                #pragma unroll
                for (int j = 0; j < TN; j++)
                    acc[i][j] += regM[i] * regN[j];
        }
        __syncthreads();
    }

    #pragma unroll
    for (int i = 0; i < TM; i++) {
        const int li = threadRow * TM + i;          // local row in tile
        if (rowBase + li >= cnt) continue;          // padding row: skip store
        const int tok = rowmap[li];
        const float rs = g_s0[tok];
        #pragma unroll
        for (int j = 0; j < TN; j += 4) {
            const int col = blockIdx.x * BN + threadCol * TN + j;
            float4 b4  = *(const float4*)(bb + threadCol * TN + j);
            float4 old = *(const float4*)(C + (size_t)tok * HID + col);
            float4 v;
            v.x = old.x + (acc[i][j + 0] + b4.x) * rs;
            v.y = old.y + (acc[i][j + 1] + b4.y) * rs;
            v.z = old.z + (acc[i][j + 2] + b4.z) * rs;
            v.w = old.w + (acc[i][j + 3] + b4.w) * rs;
            *(float4*)(C + (size_t)tok * HID + col) = v;
        }
    }
}

// ---------------------------------------------------------------------------
// Gating: per token, 10 dot products over HID (8 gate logits + 2 coef logits),
// softmax both, argmax expert (first-max like jnp.argmax), atomic bucket.
// ---------------------------------------------------------------------------
__global__ __launch_bounds__(128)
void gating_kernel(const float* __restrict__ h,
                   const float* __restrict__ gate_W,   // [HID, 8]
                   const float* __restrict__ coef_W,   // [HID, 2]
                   const float* __restrict__ coef_b)   // [2]
{
    const int n = blockIdx.x;
    const int t = threadIdx.x;
    float acc[10];
    #pragma unroll
    for (int j = 0; j < 10; j++) acc[j] = 0.0f;

    const float* hr = h + (size_t)n * HID;
    for (int k = t; k < HID; k += 128) {
        const float hv = hr[k];
        #pragma unroll
        for (int j = 0; j < 8; j++) acc[j] += hv * gate_W[k * 8 + j];
        acc[8] += hv * coef_W[k * 2 + 0];
        acc[9] += hv * coef_W[k * 2 + 1];
    }

    #pragma unroll
    for (int j = 0; j < 10; j++)
        #pragma unroll
        for (int o = 16; o > 0; o >>= 1)
            acc[j] += __shfl_down_sync(0xffffffffu, acc[j], o);

    __shared__ float red[4][10];
    const int warp = t >> 5, lane = t & 31;
    if (lane == 0) {
        #pragma unroll
        for (int j = 0; j < 10; j++) red[warp][j] = acc[j];
    }
    __syncthreads();

    if (t == 0) {
        float v[10];
        #pragma unroll
        for (int j = 0; j < 10; j++)
            v[j] = red[0][j] + red[1][j] + red[2][j] + red[3][j];

        // gate: argmax (first-max) + softmax prob of the max
        float lmax = v[0]; int idx = 0;
        #pragma unroll
        for (int j = 1; j < 8; j++)
            if (v[j] > lmax) { lmax = v[j]; idx = j; }
        float s = 0.0f;
        #pragma unroll
        for (int j = 0; j < 8; j++) s += expf(v[j] - lmax);
        const float gate = 1.0f / s;

        // 2-way coef softmax
        const float c0 = v[8] + coef_b[0];
        const float c1 = v[9] + coef_b[1];
        const float cm = fmaxf(c0, c1);
        const float e0 = expf(c0 - cm), e1 = expf(c1 - cm);
        const float inv = 1.0f / (e0 + e1);

        g_s0[n] = gate * e0 * inv;   // coef0 * gate
        g_s1[n] = e1 * inv;          // coef1

        const int pos = atomicAdd(&g_counts[idx], 1);
        g_perm[idx * N_TOK + pos] = n;
    }
}

// ---------------------------------------------------------------------------
extern "C" void kernel_launch(void* const* d_in, const int* in_sizes, int n_in,
                              void* d_out, int out_size)
{
    const float* x        = (const float*)d_in[0];
    const float* enc_W    = (const float*)d_in[1];
    const float* enc_b    = (const float*)d_in[2];
    const float* gate_W   = (const float*)d_in[3];
    const float* expert_W = (const float*)d_in[4];
    const float* expert_b = (const float*)d_in[5];
    const float* res_W    = (const float*)d_in[6];
    const float* res_b    = (const float*)d_in[7];
    const float* coef_W   = (const float*)d_in[8];
    const float* coef_b   = (const float*)d_in[9];
    const float* dec_W    = (const float*)d_in[10];
    const float* dec_b    = (const float*)d_in[11];
    float* out = (float*)d_out;

    float *hp, *up, *s1p;
    cudaGetSymbolAddress((void**)&hp,  g_h);
    cudaGetSymbolAddress((void**)&up,  g_u);
    cudaGetSymbolAddress((void**)&s1p, g_s1);

    zero_counts_kernel<<<1, 32>>>();

    // h = relu(x @ enc_W + enc_b)   [16384 x 2048]
    sgemm128<0><<<dim3(HID / 128, N_TOK / 128), 256>>>(
        x, enc_W, enc_b, hp, N_TOK, HID, IN_DIM, nullptr);

    // gating: idx, s0 = coef0*gate, s1 = coef1, expert buckets
    gating_kernel<<<N_TOK, 128>>>(hp, gate_W, coef_W, coef_b);

    // u = (h @ res_W + res_b) * s1
    sgemm128<1><<<dim3(HID / 128, N_TOK / 128), 256>>>(
        hp, res_W, res_b, up, N_TOK, HID, HID, s1p);

    // u += (h @ W_e + b_e) * s0   (grouped top-1 expert dispatch)
    sgemm128_grouped<<<dim3(HID / 128, N_TOK / 128, NEXP), 256>>>(
        hp, expert_W, expert_b, up);

    // out = u @ dec_W + dec_b     [16384 x 1024]
    sgemm128<2><<<dim3(IN_DIM / 128, N_TOK / 128), 256>>>(
        up, dec_W, dec_b, out, N_TOK, IN_DIM, HID, nullptr);
}